// round 7
// baseline (speedup 1.0000x reference)
#include <cuda_runtime.h>
#include <cuda_fp16.h>

// ---------------- problem constants ----------------
#define N_NODES   300000
#define NUM_USERS 200000
#define EMB       64
#define NNZ_E     5000000
#define ROW_U4    (EMB / 8)                  // 8 uint4 (16B) per fp16 row
#define NB_SCAN   ((N_NODES + 1023) / 1024)  // 293
#define VAL_SCALE 8191.0f
#define VAL_INV   (1.0f / 8191.0f)

// ---------------- device scratch (static; no allocations allowed) ----------------
__device__ uint4              g_t0[N_NODES * ROW_U4];   // fp16 tables (128B/row)
__device__ uint4              g_t1[N_NODES * ROW_U4];
__device__ uint4              g_t2[N_NODES * ROW_U4];
__device__ int                g_cnt[N_NODES];
__device__ int2               g_rowse[N_NODES];         // (start, end)
__device__ int                g_rowptr[N_NODES];        // compact start (scatter)
__device__ unsigned char      g_rank[NNZ_E];            // within-row rank (uint8)
__device__ unsigned           g_edge[NNZ_E];            // col(19b) | val13<<19
__device__ unsigned long long g_state[NB_SCAN];         // flag<<32 | sum

// ---------------- helpers ----------------
__device__ __forceinline__ unsigned pack_h2(float a, float b) {
    __half2 h = __floats2half2_rn(a, b);
    return *(unsigned*)&h;
}
__device__ __forceinline__ float2 unpack_h2(unsigned u) {
    return __half22float2(*(__half2*)&u);
}
__device__ __forceinline__ void acc_add(float* a, uint4 q, float v) {
    float2 f;
    f = unpack_h2(q.x); a[0] = fmaf(v, f.x, a[0]); a[1] = fmaf(v, f.y, a[1]);
    f = unpack_h2(q.y); a[2] = fmaf(v, f.x, a[2]); a[3] = fmaf(v, f.y, a[3]);
    f = unpack_h2(q.z); a[4] = fmaf(v, f.x, a[4]); a[5] = fmaf(v, f.y, a[5]);
    f = unpack_h2(q.w); a[6] = fmaf(v, f.x, a[6]); a[7] = fmaf(v, f.y, a[7]);
}

// ---------------- init: ego(fp32) -> g_t0 (fp16), zero cnt + scan state ----------------
__global__ void k_init16(const float4* __restrict__ ue,
                         const float4* __restrict__ ie) {
    int i = blockIdx.x * blockDim.x + threadIdx.x;
    if (i < N_NODES) g_cnt[i] = 0;
    if (i < NB_SCAN) g_state[i] = 0ULL;
    if (i >= N_NODES * ROW_U4) return;
    float4 a, b;
    if (i < NUM_USERS * ROW_U4) {
        a = ue[i * 2]; b = ue[i * 2 + 1];
    } else {
        int j = i - NUM_USERS * ROW_U4;
        a = ie[j * 2]; b = ie[j * 2 + 1];
    }
    uint4 o;
    o.x = pack_h2(a.x, a.y); o.y = pack_h2(a.z, a.w);
    o.z = pack_h2(b.x, b.y); o.w = pack_h2(b.z, b.w);
    g_t0[i] = o;
}

// ---------------- hist: count + record within-row rank (8 edges/thread) ----------------
__global__ void k_hist(const int4* __restrict__ row4) {
    int t = blockIdx.x * blockDim.x + threadIdx.x;
    if (t >= NNZ_E / 8) return;
    int4 ra = __ldg(&row4[t * 2]);
    int4 rb = __ldg(&row4[t * 2 + 1]);
    uchar4 ka, kb;
    ka.x = (unsigned char)atomicAdd(&g_cnt[ra.x], 1);
    ka.y = (unsigned char)atomicAdd(&g_cnt[ra.y], 1);
    ka.z = (unsigned char)atomicAdd(&g_cnt[ra.z], 1);
    ka.w = (unsigned char)atomicAdd(&g_cnt[ra.w], 1);
    kb.x = (unsigned char)atomicAdd(&g_cnt[rb.x], 1);
    kb.y = (unsigned char)atomicAdd(&g_cnt[rb.y], 1);
    kb.z = (unsigned char)atomicAdd(&g_cnt[rb.z], 1);
    kb.w = (unsigned char)atomicAdd(&g_cnt[rb.w], 1);
    uchar4* rk4 = (uchar4*)g_rank;
    rk4[t * 2]     = ka;
    rk4[t * 2 + 1] = kb;
}

// ---------------- single-pass scan with decoupled lookback ----------------
__global__ void __launch_bounds__(1024)
k_scan_lb() {
    __shared__ int sh[1024];
    __shared__ int s_prefix;
    int tid = threadIdx.x;
    int bid = blockIdx.x;
    int i = bid * 1024 + tid;
    int v = (i < N_NODES) ? g_cnt[i] : 0;

    sh[tid] = v;
    for (int off = 1; off < 1024; off <<= 1) {
        __syncthreads();
        int t = (tid >= off) ? sh[tid - off] : 0;
        __syncthreads();
        sh[tid] += t;
    }
    int incl = sh[tid];
    __syncthreads();
    int agg = sh[1023];

    if (tid == 1023) {
        unsigned long long pkt =
            ((bid == 0 ? 2ULL : 1ULL) << 32) | (unsigned)agg;
        atomicExch(&g_state[bid], pkt);
    }
    if (tid == 0) s_prefix = 0;

    if (bid > 0 && tid < 32) {
        int exc = 0;
        int j = bid - 1;
        while (true) {
            int idx = j - tid;
            unsigned long long pkt = 0;
            if (idx >= 0) {
                do { pkt = atomicAdd(&g_state[idx], 0ULL); }
                while (!(pkt >> 32));
            }
            unsigned flag = (idx >= 0) ? (unsigned)(pkt >> 32) : 0u;
            int val = (int)(unsigned)(pkt & 0xffffffffu);
            unsigned ball = __ballot_sync(0xffffffffu, flag == 2u);
            if (ball) {
                int fp = __ffs(ball) - 1;
                int contrib = (tid <= fp && idx >= 0) ? val : 0;
                exc += __reduce_add_sync(0xffffffffu, contrib);
                break;
            } else {
                int contrib = (idx >= 0) ? val : 0;
                exc += __reduce_add_sync(0xffffffffu, contrib);
                j -= 32;
                if (j < 0) break;
            }
        }
        if (tid == 0) {
            s_prefix = exc;
            atomicExch(&g_state[bid],
                       (2ULL << 32) | (unsigned)(exc + agg));
        }
    }
    __syncthreads();

    if (i < N_NODES) {
        int base = s_prefix;
        int rend = base + incl;
        int rp = rend - v;
        g_rowse[i] = make_int2(rp, rend);
        g_rowptr[i] = rp;
    }
}

// ---------------- scatter: NO atomics — pos = rowptr[row] + rank ----------------
__global__ void k_scatter(const int4* __restrict__ row4,
                          const int4* __restrict__ col4,
                          const float4* __restrict__ val4) {
    int t = blockIdx.x * blockDim.x + threadIdx.x;
    if (t >= NNZ_E / 8) return;
    const uchar4* rk4 = (const uchar4*)g_rank;
#pragma unroll
    for (int h = 0; h < 2; h++) {
        int    u = t * 2 + h;
        int4   r = __ldg(&row4[u]);
        int4   c = __ldg(&col4[u]);
        float4 v = __ldg(&val4[u]);
        uchar4 k = rk4[u];
        int p0 = __ldg(&g_rowptr[r.x]) + k.x;
        int p1 = __ldg(&g_rowptr[r.y]) + k.y;
        int p2 = __ldg(&g_rowptr[r.z]) + k.z;
        int p3 = __ldg(&g_rowptr[r.w]) + k.w;
        g_edge[p0] = (unsigned)c.x | (__float2uint_rn(v.x * VAL_SCALE) << 19);
        g_edge[p1] = (unsigned)c.y | (__float2uint_rn(v.y * VAL_SCALE) << 19);
        g_edge[p2] = (unsigned)c.z | (__float2uint_rn(v.z * VAL_SCALE) << 19);
        g_edge[p3] = (unsigned)c.w | (__float2uint_rn(v.w * VAL_SCALE) << 19);
    }
}

// ---------------- SpMM inner loop (unroll-2) ----------------
__device__ __forceinline__ void spmm_row(const uint4* __restrict__ tin,
                                          int s, int e, int lane, float* acc) {
    int i = s;
    for (; i + 1 < e; i += 2) {
        unsigned p0 = __ldg(&g_edge[i]);
        unsigned p1 = __ldg(&g_edge[i + 1]);
        uint4 q0 = __ldg(&tin[((p0 & 0x7FFFFu) << 3) + lane]);
        uint4 q1 = __ldg(&tin[((p1 & 0x7FFFFu) << 3) + lane]);
        acc_add(acc, q0, (float)(p0 >> 19) * VAL_INV);
        acc_add(acc, q1, (float)(p1 >> 19) * VAL_INV);
    }
    if (i < e) {
        unsigned p0 = __ldg(&g_edge[i]);
        uint4 q0 = __ldg(&tin[((p0 & 0x7FFFFu) << 3) + lane]);
        acc_add(acc, q0, (float)(p0 >> 19) * VAL_INV);
    }
}

__global__ void __launch_bounds__(256)
k_spmm16(int stage) {
    const uint4* tin  = (stage == 0) ? g_t0 : g_t1;
    uint4*       tout = (stage == 0) ? g_t1 : g_t2;

    int g = blockIdx.x * blockDim.x + threadIdx.x;
    int r = g >> 3;
    if (r >= N_NODES) return;
    int lane = g & 7;

    int2 se = __ldg(&g_rowse[r]);
    float acc[8] = {0.f, 0.f, 0.f, 0.f, 0.f, 0.f, 0.f, 0.f};
    spmm_row(tin, se.x, se.y, lane, acc);

    uint4 o;
    o.x = pack_h2(acc[0], acc[1]);
    o.y = pack_h2(acc[2], acc[3]);
    o.z = pack_h2(acc[4], acc[5]);
    o.w = pack_h2(acc[6], acc[7]);
    tout[(r << 3) + lane] = o;
}

// ---------------- SpMM stage 2 fused with combine ----------------
__global__ void __launch_bounds__(256)
k_spmm_final(float4* __restrict__ out) {
    int g = blockIdx.x * blockDim.x + threadIdx.x;
    int r = g >> 3;
    if (r >= N_NODES) return;
    int lane = g & 7;

    int2 se = __ldg(&g_rowse[r]);
    float acc[8] = {0.f, 0.f, 0.f, 0.f, 0.f, 0.f, 0.f, 0.f};
    spmm_row(g_t2, se.x, se.y, lane, acc);

    int idx = (r << 3) + lane;
    uint4 a = __ldg(&g_t0[idx]);
    uint4 b = __ldg(&g_t1[idx]);
    uint4 c = __ldg(&g_t2[idx]);
    acc_add(acc, a, 1.0f);
    acc_add(acc, b, 1.0f);
    acc_add(acc, c, 1.0f);

    float4 o0 = make_float4(acc[0] * 0.25f, acc[1] * 0.25f,
                            acc[2] * 0.25f, acc[3] * 0.25f);
    float4 o1 = make_float4(acc[4] * 0.25f, acc[5] * 0.25f,
                            acc[6] * 0.25f, acc[7] * 0.25f);
    int fo = (r << 4) + (lane << 1);
    __stcs(&out[fo], o0);
    __stcs(&out[fo + 1], o1);
}

// ---------------- launch ----------------
extern "C" void kernel_launch(void* const* d_in, const int* in_sizes, int n_in,
                              void* d_out, int out_size) {
    const float* user_emb = (const float*)d_in[0];
    const float* item_emb = (const float*)d_in[1];
    const int*   edge_row = (const int*)  d_in[2];
    const int*   edge_col = (const int*)  d_in[3];
    const float* edge_val = (const float*)d_in[4];
    float*       out      = (float*)d_out;

    const int TB = 256;
    const int gInit  = (N_NODES * ROW_U4 + TB - 1) / TB;
    const int gEdge8 = (NNZ_E / 8 + TB - 1) / TB;
    const int gSpmm  = (N_NODES * 8 + TB - 1) / TB;

    k_init16<<<gInit, TB>>>((const float4*)user_emb, (const float4*)item_emb);
    k_hist<<<gEdge8, TB>>>((const int4*)edge_row);
    k_scan_lb<<<NB_SCAN, 1024>>>();
    k_scatter<<<gEdge8, TB>>>((const int4*)edge_row, (const int4*)edge_col,
                              (const float4*)edge_val);

    k_spmm16<<<gSpmm, TB>>>(0);                 // t0 -> t1
    k_spmm16<<<gSpmm, TB>>>(1);                 // t1 -> t2
    k_spmm_final<<<gSpmm, TB>>>((float4*)out);  // t2 -> out (fused combine)
}

// round 8
// speedup vs baseline: 1.0063x; 1.0063x over previous
#include <cuda_runtime.h>
#include <cuda_fp16.h>

// ---------------- problem constants ----------------
#define N_NODES   300000
#define NUM_USERS 200000
#define EMB       64
#define NNZ_E     5000000
#define ROW_U4    (EMB / 8)                  // 8 uint4 (16B) per fp16 row
#define NB_SCAN   ((N_NODES + 1023) / 1024)  // 293
#define VAL_SCALE 8191.0f
#define VAL_INV   (1.0f / 8191.0f)

#define G_INIT_BLKS ((N_NODES * ROW_U4) / 256)        // 9375 (exact)
#define G_HIST_BLKS ((NNZ_E / 8 + 255) / 256)         // 2442

// ---------------- device scratch (zero-initialized at load; invariants
// restored by the kernels themselves each call) ----------------
__device__ uint4              g_t0[N_NODES * ROW_U4];   // fp16 tables (128B/row)
__device__ uint4              g_t1[N_NODES * ROW_U4];
__device__ uint4              g_t2[N_NODES * ROW_U4];
__device__ int                g_cnt[N_NODES];           // ALWAYS 0 between calls
__device__ int2               g_rowse[N_NODES];         // (start, end)
__device__ int                g_cursor[N_NODES];
__device__ unsigned           g_edge[NNZ_E];            // col(19b) | val13<<19
__device__ unsigned long long g_state[NB_SCAN];         // ALWAYS 0 between calls

// ---------------- helpers ----------------
__device__ __forceinline__ unsigned pack_h2(float a, float b) {
    __half2 h = __floats2half2_rn(a, b);
    return *(unsigned*)&h;
}
__device__ __forceinline__ float2 unpack_h2(unsigned u) {
    return __half22float2(*(__half2*)&u);
}
__device__ __forceinline__ void acc_add(float* a, uint4 q, float v) {
    float2 f;
    f = unpack_h2(q.x); a[0] = fmaf(v, f.x, a[0]); a[1] = fmaf(v, f.y, a[1]);
    f = unpack_h2(q.y); a[2] = fmaf(v, f.x, a[2]); a[3] = fmaf(v, f.y, a[3]);
    f = unpack_h2(q.z); a[4] = fmaf(v, f.x, a[4]); a[5] = fmaf(v, f.y, a[5]);
    f = unpack_h2(q.w); a[6] = fmaf(v, f.x, a[6]); a[7] = fmaf(v, f.y, a[7]);
}

// ---------------- merged: table init (fp32->fp16) || edge histogram ----------------
// Safe to run concurrently: hist touches only g_cnt (pre-zeroed invariant),
// init touches only g_t0. Disjoint.
__global__ void __launch_bounds__(256)
k_init_hist(const float4* __restrict__ ue,
            const float4* __restrict__ ie,
            const int4*   __restrict__ row4) {
    int bid = blockIdx.x;
    if (bid < G_HIST_BLKS) {
        // ---- histogram: 8 edges/thread, non-returning atomics (RED) ----
        int t = bid * 256 + threadIdx.x;
        if (t >= NNZ_E / 8) return;
        int4 ra = __ldg(&row4[t * 2]);
        int4 rb = __ldg(&row4[t * 2 + 1]);
        atomicAdd(&g_cnt[ra.x], 1);
        atomicAdd(&g_cnt[ra.y], 1);
        atomicAdd(&g_cnt[ra.z], 1);
        atomicAdd(&g_cnt[ra.w], 1);
        atomicAdd(&g_cnt[rb.x], 1);
        atomicAdd(&g_cnt[rb.y], 1);
        atomicAdd(&g_cnt[rb.z], 1);
        atomicAdd(&g_cnt[rb.w], 1);
    } else {
        // ---- table init ----
        int i = (bid - G_HIST_BLKS) * 256 + threadIdx.x;
        if (i >= N_NODES * ROW_U4) return;
        float4 a, b;
        if (i < NUM_USERS * ROW_U4) {
            a = __ldg(&ue[i * 2]); b = __ldg(&ue[i * 2 + 1]);
        } else {
            int j = i - NUM_USERS * ROW_U4;
            a = __ldg(&ie[j * 2]); b = __ldg(&ie[j * 2 + 1]);
        }
        uint4 o;
        o.x = pack_h2(a.x, a.y); o.y = pack_h2(a.z, a.w);
        o.z = pack_h2(b.x, b.y); o.w = pack_h2(b.z, b.w);
        g_t0[i] = o;
    }
}

// ---------------- single-pass scan with decoupled lookback ----------------
// Also restores g_cnt[i]=0 for the next invocation.
__global__ void __launch_bounds__(1024)
k_scan_lb() {
    __shared__ int sh[1024];
    __shared__ int s_prefix;
    int tid = threadIdx.x;
    int bid = blockIdx.x;
    int i = bid * 1024 + tid;
    int v = (i < N_NODES) ? g_cnt[i] : 0;
    if (i < N_NODES) g_cnt[i] = 0;          // restore invariant

    sh[tid] = v;
    for (int off = 1; off < 1024; off <<= 1) {
        __syncthreads();
        int t = (tid >= off) ? sh[tid - off] : 0;
        __syncthreads();
        sh[tid] += t;
    }
    int incl = sh[tid];
    __syncthreads();
    int agg = sh[1023];

    if (tid == 1023) {
        unsigned long long pkt =
            ((bid == 0 ? 2ULL : 1ULL) << 32) | (unsigned)agg;
        atomicExch(&g_state[bid], pkt);
    }
    if (tid == 0) s_prefix = 0;

    if (bid > 0 && tid < 32) {
        int exc = 0;
        int j = bid - 1;
        while (true) {
            int idx = j - tid;
            unsigned long long pkt = 0;
            if (idx >= 0) {
                do { pkt = atomicAdd(&g_state[idx], 0ULL); }
                while (!(pkt >> 32));
            }
            unsigned flag = (idx >= 0) ? (unsigned)(pkt >> 32) : 0u;
            int val = (int)(unsigned)(pkt & 0xffffffffu);
            unsigned ball = __ballot_sync(0xffffffffu, flag == 2u);
            if (ball) {
                int fp = __ffs(ball) - 1;
                int contrib = (tid <= fp && idx >= 0) ? val : 0;
                exc += __reduce_add_sync(0xffffffffu, contrib);
                break;
            } else {
                int contrib = (idx >= 0) ? val : 0;
                exc += __reduce_add_sync(0xffffffffu, contrib);
                j -= 32;
                if (j < 0) break;
            }
        }
        if (tid == 0) {
            s_prefix = exc;
            atomicExch(&g_state[bid],
                       (2ULL << 32) | (unsigned)(exc + agg));
        }
    }
    __syncthreads();

    if (i < N_NODES) {
        int base = s_prefix;
        int rend = base + incl;
        int rp = rend - v;
        g_rowse[i] = make_int2(rp, rend);
        g_cursor[i] = rp;
    }
}

// ---------------- scatter: cursor atomics, batched for MLP ----------------
// Also restores g_state[t]=0 for the next invocation.
__global__ void __launch_bounds__(256)
k_scatter(const int4* __restrict__ row4,
          const int4* __restrict__ col4,
          const float4* __restrict__ val4) {
    int t = blockIdx.x * blockDim.x + threadIdx.x;
    if (t < NB_SCAN) g_state[t] = 0ULL;     // restore invariant
    if (t >= NNZ_E / 8) return;

    int4   r0 = __ldg(&row4[t * 2]);
    int4   r1 = __ldg(&row4[t * 2 + 1]);
    int4   c0 = __ldg(&col4[t * 2]);
    int4   c1 = __ldg(&col4[t * 2 + 1]);
    float4 v0 = __ldg(&val4[t * 2]);
    float4 v1 = __ldg(&val4[t * 2 + 1]);

    unsigned q[8];
    q[0] = (unsigned)c0.x | (__float2uint_rn(v0.x * VAL_SCALE) << 19);
    q[1] = (unsigned)c0.y | (__float2uint_rn(v0.y * VAL_SCALE) << 19);
    q[2] = (unsigned)c0.z | (__float2uint_rn(v0.z * VAL_SCALE) << 19);
    q[3] = (unsigned)c0.w | (__float2uint_rn(v0.w * VAL_SCALE) << 19);
    q[4] = (unsigned)c1.x | (__float2uint_rn(v1.x * VAL_SCALE) << 19);
    q[5] = (unsigned)c1.y | (__float2uint_rn(v1.y * VAL_SCALE) << 19);
    q[6] = (unsigned)c1.z | (__float2uint_rn(v1.z * VAL_SCALE) << 19);
    q[7] = (unsigned)c1.w | (__float2uint_rn(v1.w * VAL_SCALE) << 19);

    // issue all 8 independent atomics before any dependent store
    int p[8];
    p[0] = atomicAdd(&g_cursor[r0.x], 1);
    p[1] = atomicAdd(&g_cursor[r0.y], 1);
    p[2] = atomicAdd(&g_cursor[r0.z], 1);
    p[3] = atomicAdd(&g_cursor[r0.w], 1);
    p[4] = atomicAdd(&g_cursor[r1.x], 1);
    p[5] = atomicAdd(&g_cursor[r1.y], 1);
    p[6] = atomicAdd(&g_cursor[r1.z], 1);
    p[7] = atomicAdd(&g_cursor[r1.w], 1);

#pragma unroll
    for (int k = 0; k < 8; k++) g_edge[p[k]] = q[k];
}

// ---------------- SpMM inner loop (unroll-2) ----------------
__device__ __forceinline__ void spmm_row(const uint4* __restrict__ tin,
                                          int s, int e, int lane, float* acc) {
    int i = s;
    for (; i + 1 < e; i += 2) {
        unsigned p0 = __ldg(&g_edge[i]);
        unsigned p1 = __ldg(&g_edge[i + 1]);
        uint4 q0 = __ldg(&tin[((p0 & 0x7FFFFu) << 3) + lane]);
        uint4 q1 = __ldg(&tin[((p1 & 0x7FFFFu) << 3) + lane]);
        acc_add(acc, q0, (float)(p0 >> 19) * VAL_INV);
        acc_add(acc, q1, (float)(p1 >> 19) * VAL_INV);
    }
    if (i < e) {
        unsigned p0 = __ldg(&g_edge[i]);
        uint4 q0 = __ldg(&tin[((p0 & 0x7FFFFu) << 3) + lane]);
        acc_add(acc, q0, (float)(p0 >> 19) * VAL_INV);
    }
}

__global__ void __launch_bounds__(256)
k_spmm16(int stage) {
    const uint4* tin  = (stage == 0) ? g_t0 : g_t1;
    uint4*       tout = (stage == 0) ? g_t1 : g_t2;

    int g = blockIdx.x * blockDim.x + threadIdx.x;
    int r = g >> 3;
    if (r >= N_NODES) return;
    int lane = g & 7;

    int2 se = __ldg(&g_rowse[r]);
    float acc[8] = {0.f, 0.f, 0.f, 0.f, 0.f, 0.f, 0.f, 0.f};
    spmm_row(tin, se.x, se.y, lane, acc);

    uint4 o;
    o.x = pack_h2(acc[0], acc[1]);
    o.y = pack_h2(acc[2], acc[3]);
    o.z = pack_h2(acc[4], acc[5]);
    o.w = pack_h2(acc[6], acc[7]);
    tout[(r << 3) + lane] = o;
}

// ---------------- SpMM stage 2 fused with combine ----------------
__global__ void __launch_bounds__(256)
k_spmm_final(float4* __restrict__ out) {
    int g = blockIdx.x * blockDim.x + threadIdx.x;
    int r = g >> 3;
    if (r >= N_NODES) return;
    int lane = g & 7;

    int2 se = __ldg(&g_rowse[r]);
    float acc[8] = {0.f, 0.f, 0.f, 0.f, 0.f, 0.f, 0.f, 0.f};
    spmm_row(g_t2, se.x, se.y, lane, acc);

    int idx = (r << 3) + lane;
    uint4 a = __ldg(&g_t0[idx]);
    uint4 b = __ldg(&g_t1[idx]);
    uint4 c = __ldg(&g_t2[idx]);
    acc_add(acc, a, 1.0f);
    acc_add(acc, b, 1.0f);
    acc_add(acc, c, 1.0f);

    float4 o0 = make_float4(acc[0] * 0.25f, acc[1] * 0.25f,
                            acc[2] * 0.25f, acc[3] * 0.25f);
    float4 o1 = make_float4(acc[4] * 0.25f, acc[5] * 0.25f,
                            acc[6] * 0.25f, acc[7] * 0.25f);
    int fo = (r << 4) + (lane << 1);
    __stcs(&out[fo], o0);
    __stcs(&out[fo + 1], o1);
}

// ---------------- launch ----------------
extern "C" void kernel_launch(void* const* d_in, const int* in_sizes, int n_in,
                              void* d_out, int out_size) {
    const float* user_emb = (const float*)d_in[0];
    const float* item_emb = (const float*)d_in[1];
    const int*   edge_row = (const int*)  d_in[2];
    const int*   edge_col = (const int*)  d_in[3];
    const float* edge_val = (const float*)d_in[4];
    float*       out      = (float*)d_out;

    const int TB = 256;
    const int gMerge = G_HIST_BLKS + G_INIT_BLKS;
    const int gEdge8 = (NNZ_E / 8 + TB - 1) / TB;
    const int gSpmm  = (N_NODES * 8 + TB - 1) / TB;

    k_init_hist<<<gMerge, TB>>>((const float4*)user_emb,
                                (const float4*)item_emb,
                                (const int4*)edge_row);
    k_scan_lb<<<NB_SCAN, 1024>>>();
    k_scatter<<<gEdge8, TB>>>((const int4*)edge_row, (const int4*)edge_col,
                              (const float4*)edge_val);

    k_spmm16<<<gSpmm, TB>>>(0);                 // t0 -> t1
    k_spmm16<<<gSpmm, TB>>>(1);                 // t1 -> t2
    k_spmm_final<<<gSpmm, TB>>>((float4*)out);  // t2 -> out (fused combine)
}